// round 14
// baseline (speedup 1.0000x reference)
#include <cuda_runtime.h>
#include <cuda_bf16.h>
#include <cuda_fp16.h>
#include <math.h>

#define SDIM 1024
#define EDIM 1024
#define BDIM 4
#define HDIM 16
#define DDIM 64
#define BH   64
#define MTOT 4096

typedef __nv_bfloat16  bf16;
typedef __nv_bfloat162 bf162;

// ---------------- scratch (device globals; no allocation) ----------------
__device__ float g_p0[BH * SDIM * DDIM];
__device__ float g_p1[BH * SDIM * DDIM];
__device__ float g_v [BH * SDIM * DDIM];
__device__ float g_s2[BDIM * EDIM];
__device__ float g_M [BH * DDIM * DDIM];
__device__ float g_xsum[BDIM * EDIM];
__device__ float g_val[MTOT * EDIM];
__device__ __half g_vth[BH * DDIM * SDIM], g_vtl[BH * DDIM * SDIM];

// ---------------- helpers -------------------------------------------------
__device__ __forceinline__ unsigned s2u(const void* p) {
    return (unsigned)__cvta_generic_to_shared(p);
}
__device__ __forceinline__ void ldsm4(unsigned* r, unsigned addr) {
    asm volatile("ldmatrix.sync.aligned.m8n8.x4.shared.b16 {%0,%1,%2,%3}, [%4];"
                 : "=r"(r[0]), "=r"(r[1]), "=r"(r[2]), "=r"(r[3]) : "r"(addr));
}
__device__ __forceinline__ void mma16816(float* c, const unsigned* a, const unsigned* b) {
    asm volatile("mma.sync.aligned.m16n8k16.row.col.f32.bf16.bf16.f32 "
                 "{%0,%1,%2,%3}, {%4,%5,%6,%7}, {%8,%9}, {%0,%1,%2,%3};"
                 : "+f"(c[0]), "+f"(c[1]), "+f"(c[2]), "+f"(c[3])
                 : "r"(a[0]), "r"(a[1]), "r"(a[2]), "r"(a[3]), "r"(b[0]), "r"(b[1]));
}
__device__ __forceinline__ void mma16816h(float* c, const unsigned* a, const unsigned* b) {
    asm volatile("mma.sync.aligned.m16n8k16.row.col.f32.f16.f16.f32 "
                 "{%0,%1,%2,%3}, {%4,%5,%6,%7}, {%8,%9}, {%0,%1,%2,%3};"
                 : "+f"(c[0]), "+f"(c[1]), "+f"(c[2]), "+f"(c[3])
                 : "r"(a[0]), "r"(a[1]), "r"(a[2]), "r"(a[3]), "r"(b[0]), "r"(b[1]));
}
__device__ __forceinline__ void h2split(float x, float y, unsigned& hi, unsigned& lo) {
    __half2 h = __floats2half2_rn(x, y);
    float hx = __low2float(h), hy = __high2float(h);
    __half2 l = __floats2half2_rn(x - hx, y - hy);
    hi = *(unsigned*)&h;
    lo = *(unsigned*)&l;
}

// ---------------- xsum[b][e] = sum_s x[b,s,e] -----------------------------
__global__ void xsum_kernel(const float* __restrict__ X)
{
    int b = blockIdx.y;
    int e = blockIdx.x * 256 + threadIdx.x;
    const float* p = X + ((size_t)b * SDIM) * EDIM + e;
    float acc = 0.f;
    for (int s = 0; s < SDIM; s++) acc += p[(size_t)s * EDIM];
    g_xsum[b * EDIM + e] = acc;
}

// ---------------- s2[b*1024+col] = xsum[b] . W2[col] + 1024*b2[col] -------
__global__ void s2small_kernel(const float* __restrict__ W2, const float* __restrict__ b2)
{
    int w = threadIdx.x >> 5, lane = threadIdx.x & 31;
    int b = blockIdx.y;
    int col = blockIdx.x * 8 + w;
    const float* wp = W2 + (size_t)col * EDIM;
    const float* xp = g_xsum + b * EDIM;
    float acc = 0.f;
    for (int e = lane; e < EDIM; e += 32) acc += xp[e] * wp[e];
#pragma unroll
    for (int o = 16; o > 0; o >>= 1) acc += __shfl_xor_sync(0xffffffffu, acc, o);
    if (lane == 0) g_s2[b * EDIM + col] = acc + 1024.0f * b2[col];
}

// ---------------- M[bh,(a,c)] = sum_d A[(a,c),d]*s2[bh,d] -----------------
__global__ void __launch_bounds__(256) m_kernel(const float* __restrict__ A)
{
    __shared__ float s2s[64][68];
    __shared__ float As[64][68];
    const int tid = threadIdx.x;
    const int r0 = blockIdx.x * 64;

    for (int i = tid; i < 1024; i += 256) {
        int r = i >> 4, c4 = (i & 15) * 4;
        float4 v = *(const float4*)&g_s2[(r >> 4) * EDIM + (r & 15) * 64 + c4];
        *(float4*)&s2s[r][c4] = v;
    }
    for (int i = tid; i < 1024; i += 256) {
        int r = i >> 4, c4 = (i & 15) * 4;
        float4 v = *(const float4*)&A[(size_t)(r0 + r) * 64 + c4];
        *(float4*)&As[r][c4] = v;
    }
    __syncthreads();

    const int row = tid & 63, bh0 = (tid >> 6) * 16;
    float acc[16];
#pragma unroll
    for (int j = 0; j < 16; j++) acc[j] = 0.f;
#pragma unroll
    for (int d4 = 0; d4 < 16; d4++) {
        float4 a = *(float4*)&As[row][d4 * 4];
#pragma unroll
        for (int j = 0; j < 16; j++) {
            float4 s = *(float4*)&s2s[bh0 + j][d4 * 4];
            acc[j] += a.x * s.x + a.y * s.y + a.z * s.z + a.w * s.w;
        }
    }
#pragma unroll
    for (int j = 0; j < 16; j++)
        g_M[(size_t)(bh0 + j) * 4096 + r0 + row] = acc[j];
}

// ---------------- proven tensor-core NT GEMM (bf16 split-3) ---------------
#define KT    32
#define LDSS  40

template <int MODE>
__device__ __forceinline__ void gemm_core(
    const float* __restrict__ X, const float* __restrict__ W,
    const float* __restrict__ bias, float* __restrict__ Out)
{
    __shared__ bf16 Ah[128 * LDSS];
    __shared__ bf16 Al[128 * LDSS];
    __shared__ bf16 Bh[128 * LDSS];
    __shared__ bf16 Bl[128 * LDSS];

    const int tid  = threadIdx.x;
    const int lane = tid & 31;
    const int wid  = tid >> 5;
    const int m0 = blockIdx.y * 128;
    const int n0 = blockIdx.x * 128;
    const int wm = (wid >> 2) * 64;
    const int wn = (wid & 3) * 32;

    float4 pa[4], pb[4];

    unsigned baA[4], baAl[4], baB[2], baBl[2];
    {
        int ar = lane & 15, ak = (lane >> 4) * 8;
#pragma unroll
        for (int mi = 0; mi < 4; mi++) {
            int off = ((wm + mi * 16 + ar) * LDSS + ak) * 2;
            baA[mi]  = s2u(Ah) + off;
            baAl[mi] = s2u(Al) + off;
        }
        int nr = (lane & 7) + ((lane >> 4) & 1) * 8;
        int nk = ((lane >> 3) & 1) * 8;
#pragma unroll
        for (int np = 0; np < 2; np++) {
            int off = ((wn + np * 16 + nr) * LDSS + nk) * 2;
            baB[np]  = s2u(Bh) + off;
            baBl[np] = s2u(Bl) + off;
        }
    }

    float acc[4][4][4];
#pragma unroll
    for (int i = 0; i < 4; i++)
#pragma unroll
        for (int j = 0; j < 4; j++)
#pragma unroll
            for (int e = 0; e < 4; e++) acc[i][j][e] = 0.f;

    auto loadTile = [&](int k0) {
#pragma unroll
        for (int l = 0; l < 4; l++) {
            int idx = l * 256 + tid;
            int row = idx >> 3, kq = (idx & 7) * 4;
            pa[l] = *(const float4*)&X[(size_t)(m0 + row) * EDIM + k0 + kq];
            pb[l] = *(const float4*)&W[(size_t)(n0 + row) * EDIM + k0 + kq];
        }
    };
    auto storeTile = [&]() {
#pragma unroll
        for (int l = 0; l < 4; l++) {
            int idx = l * 256 + tid;
            int row = idx >> 3, kq = (idx & 7) * 4;
            int o = row * LDSS + kq;
            float4 a = pa[l];
            bf16 hx = __float2bfloat16_rn(a.x);
            bf16 hy = __float2bfloat16_rn(a.y);
            bf16 hz = __float2bfloat16_rn(a.z);
            bf16 hw = __float2bfloat16_rn(a.w);
            *(bf162*)&Ah[o]     = bf162(hx, hy);
            *(bf162*)&Ah[o + 2] = bf162(hz, hw);
            *(bf162*)&Al[o]     = bf162(
                __float2bfloat16_rn(a.x - __bfloat162float(hx)),
                __float2bfloat16_rn(a.y - __bfloat162float(hy)));
            *(bf162*)&Al[o + 2] = bf162(
                __float2bfloat16_rn(a.z - __bfloat162float(hz)),
                __float2bfloat16_rn(a.w - __bfloat162float(hw)));
            float4 b = pb[l];
            hx = __float2bfloat16_rn(b.x); hy = __float2bfloat16_rn(b.y);
            hz = __float2bfloat16_rn(b.z); hw = __float2bfloat16_rn(b.w);
            *(bf162*)&Bh[o]     = bf162(hx, hy);
            *(bf162*)&Bh[o + 2] = bf162(hz, hw);
            *(bf162*)&Bl[o]     = bf162(
                __float2bfloat16_rn(b.x - __bfloat162float(hx)),
                __float2bfloat16_rn(b.y - __bfloat162float(hy)));
            *(bf162*)&Bl[o + 2] = bf162(
                __float2bfloat16_rn(b.z - __bfloat162float(hz)),
                __float2bfloat16_rn(b.w - __bfloat162float(hw)));
        }
    };

    loadTile(0);
    storeTile();
    __syncthreads();

    for (int kt = 0; kt < EDIM / KT; kt++) {
        bool has_next = (kt + 1) < EDIM / KT;
        if (has_next) loadTile((kt + 1) * KT);

#pragma unroll
        for (int kk = 0; kk < 2; kk++) {
            unsigned boff = kk * 32;
            unsigned ah[4][4], al[4][4], bh_[4][2], bl_[4][2];
#pragma unroll
            for (int mi = 0; mi < 4; mi++) ldsm4(ah[mi], baA[mi] + boff);
#pragma unroll
            for (int np = 0; np < 2; np++) {
                unsigned r[4];
                ldsm4(r, baB[np] + boff);
                bh_[2 * np][0] = r[0]; bh_[2 * np][1] = r[1];
                bh_[2 * np + 1][0] = r[2]; bh_[2 * np + 1][1] = r[3];
            }
#pragma unroll
            for (int mi = 0; mi < 4; mi++)
#pragma unroll
                for (int ni = 0; ni < 4; ni++) mma16816(acc[mi][ni], ah[mi], bh_[ni]);

#pragma unroll
            for (int np = 0; np < 2; np++) {
                unsigned r[4];
                ldsm4(r, baBl[np] + boff);
                bl_[2 * np][0] = r[0]; bl_[2 * np][1] = r[1];
                bl_[2 * np + 1][0] = r[2]; bl_[2 * np + 1][1] = r[3];
            }
#pragma unroll
            for (int mi = 0; mi < 4; mi++)
#pragma unroll
                for (int ni = 0; ni < 4; ni++) mma16816(acc[mi][ni], ah[mi], bl_[ni]);

#pragma unroll
            for (int mi = 0; mi < 4; mi++) ldsm4(al[mi], baAl[mi] + boff);
#pragma unroll
            for (int mi = 0; mi < 4; mi++)
#pragma unroll
                for (int ni = 0; ni < 4; ni++) mma16816(acc[mi][ni], al[mi], bh_[ni]);
        }

        __syncthreads();
        if (has_next) {
            storeTile();
            __syncthreads();
        }
    }

    const int g = lane >> 2;
    const int cq = (lane & 3) * 2;
#pragma unroll
    for (int mi = 0; mi < 4; mi++) {
#pragma unroll
        for (int ni = 0; ni < 4; ni++) {
            int col = n0 + wn + ni * 8 + cq;
            float2 bia = *(const float2*)&bias[col];
#pragma unroll
            for (int half = 0; half < 2; half++) {
                int row = m0 + wm + mi * 16 + g + half * 8;
                float v0 = acc[mi][ni][half * 2 + 0] + bia.x;
                float v1 = acc[mi][ni][half * 2 + 1] + bia.y;
                if (MODE == 0) {
                    int bb = row >> 10, ss = row & 1023;
                    int h = col >> 6, d = col & 63;
                    *(float2*)&Out[(((size_t)(bb * HDIM + h) * SDIM) + ss) * DDIM + d]
                        = make_float2(v0, v1);
                } else {
                    *(float2*)&Out[(size_t)row * EDIM + col] = make_float2(v0, v1);
                }
            }
        }
    }
}

__global__ void __launch_bounds__(256, 1) gemm_proj_kernel(
    const float* __restrict__ X,
    const float* __restrict__ W0, const float* __restrict__ b0,
    const float* __restrict__ W1, const float* __restrict__ b1,
    const float* __restrict__ Wv, const float* __restrict__ bv)
{
    switch (blockIdx.z) {
        case 0:  gemm_core<0>(X, W0, b0, g_p0); break;
        case 1:  gemm_core<0>(X, W1, b1, g_p1); break;
        default: gemm_core<0>(X, Wv, bv, g_v);  break;
    }
}

__global__ void __launch_bounds__(256, 1) gemm_out_kernel(
    const float* __restrict__ Wo, const float* __restrict__ bo, float* __restrict__ Out)
{
    gemm_core<1>(g_val, Wo, bo, Out);
}

// ---- fused t + logits (3xfp16 split) + softmax, 32-row blocks ------------
// 512 threads = 16 warps: warp = (row-group rg in {0,1}, col-slice cs in 0..7).
// One staged p1 chunk serves 32 rows -> p1 L2 traffic halved vs 16-row blocks.
#define PSTR 68

__global__ void __launch_bounds__(512) lsm_kernel(float* __restrict__ attn)
{
    __shared__ float Bs[128 * PSTR];
    __shared__ float As[32 * PSTR];
    __shared__ float wmax[2][8][16];
    __shared__ float wsum[2][8][16];

    const int bh = blockIdx.y;
    const int m0 = blockIdx.x * 32;
    const int tid = threadIdx.x, lane = tid & 31, w = tid >> 5;
    const int rg = w >> 3, cs = w & 7;
    const int g = lane >> 2, t4 = lane & 3;

    const float* Pp = g_p1 + (size_t)bh * SDIM * DDIM;
    float* Op = attn + ((size_t)bh << 20) + (size_t)(m0 + rg * 16) * SDIM;

    // ---- prologue: t = (p0_tile(32x64) @ M(64x64)) * 0.125 ----
    {
        const float* Mp = g_M + (size_t)bh * 4096;
#pragma unroll
        for (int l = 0; l < 2; l++) {
            int idx = l * 512 + tid;
            int row = idx >> 4, c4 = (idx & 15) * 4;
            *(float4*)&Bs[row * PSTR + c4] = *(const float4*)&Mp[row * 64 + c4];
        }
        const float* P0p = g_p0 + ((size_t)bh * SDIM + m0) * DDIM;
        int r = tid >> 4, f4 = (tid & 15) * 4;
        *(float4*)&As[r * PSTR + f4] = *(const float4*)&P0p[r * 64 + f4];
    }
    __syncthreads();
    {
        int r = tid >> 4, c4 = (tid & 15) * 4;
        float4 tacc = make_float4(0.f, 0.f, 0.f, 0.f);
#pragma unroll 8
        for (int a = 0; a < 64; a++) {
            float pa = As[r * PSTR + a];
            float4 m = *(float4*)&Bs[a * PSTR + c4];
            tacc.x += pa * m.x; tacc.y += pa * m.y;
            tacc.z += pa * m.z; tacc.w += pa * m.w;
        }
        __syncthreads();
        tacc.x *= 0.125f; tacc.y *= 0.125f; tacc.z *= 0.125f; tacc.w *= 0.125f;
        *(float4*)&As[r * PSTR + c4] = tacc;
    }
    __syncthreads();

    // precompute fp16 hi/lo A-fragments (this warp's 16-row group)
    unsigned ahi[4][4], alo[4][4];
#pragma unroll
    for (int ks = 0; ks < 4; ks++) {
        int c0 = ks * 16 + 2 * t4;
        int r0 = rg * 16;
        float2 x0 = *(float2*)&As[(r0 + g) * PSTR + c0];
        float2 x1 = *(float2*)&As[(r0 + g + 8) * PSTR + c0];
        float2 x2 = *(float2*)&As[(r0 + g) * PSTR + c0 + 8];
        float2 x3 = *(float2*)&As[(r0 + g + 8) * PSTR + c0 + 8];
        h2split(x0.x, x0.y, ahi[ks][0], alo[ks][0]);
        h2split(x1.x, x1.y, ahi[ks][1], alo[ks][1]);
        h2split(x2.x, x2.y, ahi[ks][2], alo[ks][2]);
        h2split(x3.x, x3.y, ahi[ks][3], alo[ks][3]);
    }

    float acc[8][2][4];
#pragma unroll
    for (int c = 0; c < 8; c++)
#pragma unroll
        for (int nt = 0; nt < 2; nt++)
#pragma unroll
            for (int e = 0; e < 4; e++) acc[c][nt][e] = 0.f;

#pragma unroll 1
    for (int c = 0; c < 8; c++) {
        __syncthreads();
#pragma unroll
        for (int l = 0; l < 4; l++) {
            int idx = l * 512 + tid;
            int row = idx >> 4, f4 = idx & 15;
            float4 v = *(const float4*)&Pp[(size_t)(c * 128 + row) * 64 + f4 * 4];
            *(float4*)&Bs[row * PSTR + f4 * 4] = v;
        }
        __syncthreads();

#pragma unroll
        for (int nt = 0; nt < 2; nt++) {
            int nb = cs * 16 + nt * 8 + g;
#pragma unroll
            for (int ks = 0; ks < 4; ks++) {
                float2 p = *(float2*)&Bs[nb * PSTR + ks * 16 + 2 * t4];
                float2 q = *(float2*)&Bs[nb * PSTR + ks * 16 + 2 * t4 + 8];
                unsigned bhf[2], blf[2];
                h2split(p.x, p.y, bhf[0], blf[0]);
                h2split(q.x, q.y, bhf[1], blf[1]);
                mma16816h(acc[c][nt], ahi[ks], bhf);
                mma16816h(acc[c][nt], ahi[ks], blf);
                mma16816h(acc[c][nt], alo[ks], bhf);
            }
        }
    }

    // ---- softmax per row-group ----
    float mr0 = -1e30f, mr1 = -1e30f;
#pragma unroll
    for (int c = 0; c < 8; c++)
#pragma unroll
        for (int nt = 0; nt < 2; nt++) {
            mr0 = fmaxf(mr0, fmaxf(acc[c][nt][0], acc[c][nt][1]));
            mr1 = fmaxf(mr1, fmaxf(acc[c][nt][2], acc[c][nt][3]));
        }
#pragma unroll
    for (int o = 1; o <= 2; o <<= 1) {
        mr0 = fmaxf(mr0, __shfl_xor_sync(0xffffffffu, mr0, o));
        mr1 = fmaxf(mr1, __shfl_xor_sync(0xffffffffu, mr1, o));
    }
    if (t4 == 0) { wmax[rg][cs][g] = mr0; wmax[rg][cs][g + 8] = mr1; }
    __syncthreads();
    float M0 = -1e30f, M1 = -1e30f;
#pragma unroll
    for (int ww = 0; ww < 8; ww++) {
        M0 = fmaxf(M0, wmax[rg][ww][g]);
        M1 = fmaxf(M1, wmax[rg][ww][g + 8]);
    }

    float s0 = 0.f, s1 = 0.f;
#pragma unroll
    for (int c = 0; c < 8; c++)
#pragma unroll
        for (int nt = 0; nt < 2; nt++) {
            float e0 = __expf(acc[c][nt][0] - M0);
            float e1 = __expf(acc[c][nt][1] - M0);
            float e2 = __expf(acc[c][nt][2] - M1);
            float e3 = __expf(acc[c][nt][3] - M1);
            acc[c][nt][0] = e0; acc[c][nt][1] = e1;
            acc[c][nt][2] = e2; acc[c][nt][3] = e3;
            s0 += e0 + e1; s1 += e2 + e3;
        }
#pragma unroll
    for (int o = 1; o <= 2; o <<= 1) {
        s0 += __shfl_xor_sync(0xffffffffu, s0, o);
        s1 += __shfl_xor_sync(0xffffffffu, s1, o);
    }
    if (t4 == 0) { wsum[rg][cs][g] = s0; wsum[rg][cs][g + 8] = s1; }
    __syncthreads();
    float S0 = 0.f, S1 = 0.f;
#pragma unroll
    for (int ww = 0; ww < 8; ww++) { S0 += wsum[rg][ww][g]; S1 += wsum[rg][ww][g + 8]; }
    float inv0 = 1.0f / S0, inv1 = 1.0f / S1;

#pragma unroll
    for (int c = 0; c < 8; c++)
#pragma unroll
        for (int nt = 0; nt < 2; nt++) {
            int col = c * 128 + cs * 16 + nt * 8 + 2 * t4;
            __stcs((float2*)&Op[(size_t)g * SDIM + col],
                   make_float2(acc[c][nt][0] * inv0, acc[c][nt][1] * inv0));
            __stcs((float2*)&Op[(size_t)(g + 8) * SDIM + col],
                   make_float2(acc[c][nt][2] * inv1, acc[c][nt][3] * inv1));
        }
}

// ---------------- V transpose + fp16 split: vT[bh][d][s] ------------------
__global__ void vt_kernel()
{
    __shared__ float ts[64][65];
    int bh = blockIdx.y;
    int s0 = blockIdx.x * 64;
    int tid = threadIdx.x;
#pragma unroll
    for (int l = 0; l < 4; l++) {
        int idx = l * 256 + tid;
        int s = idx >> 4, f4 = idx & 15;
        float4 v = *(const float4*)&g_v[((size_t)bh * SDIM + s0 + s) * DDIM + f4 * 4];
        ts[s][f4 * 4 + 0] = v.x; ts[s][f4 * 4 + 1] = v.y;
        ts[s][f4 * 4 + 2] = v.z; ts[s][f4 * 4 + 3] = v.w;
    }
    __syncthreads();
#pragma unroll
    for (int l = 0; l < 4; l++) {
        int idx = l * 256 + tid;
        int d = idx >> 4, sg = (idx & 15) * 4;
        float x0 = ts[sg + 0][d], x1 = ts[sg + 1][d];
        float x2 = ts[sg + 2][d], x3 = ts[sg + 3][d];
        __half h0 = __float2half_rn(x0), h1 = __float2half_rn(x1);
        __half h2 = __float2half_rn(x2), h3 = __float2half_rn(x3);
        size_t o = ((size_t)bh * DDIM + d) * SDIM + s0 + sg;
        *(__half2*)&g_vth[o]     = __half2(h0, h1);
        *(__half2*)&g_vth[o + 2] = __half2(h2, h3);
        *(__half2*)&g_vtl[o] = __half2(__float2half_rn(x0 - __half2float(h0)),
                                       __float2half_rn(x1 - __half2float(h1)));
        *(__half2*)&g_vtl[o + 2] = __half2(__float2half_rn(x2 - __half2float(h2)),
                                           __float2half_rn(x3 - __half2float(h3)));
    }
}

// ---------------- AV: values = attn @ V, fp16 2-term TC -------------------
#define LDSS2 40
__global__ void __launch_bounds__(256, 1) av_tc_kernel(const float* __restrict__ attn)
{
    __shared__ __half Ah[128 * LDSS2];
    __shared__ __half Bh[64 * LDSS2];
    __shared__ __half Bl[64 * LDSS2];

    const int bh = blockIdx.y;
    const int bb = bh >> 4, h = bh & 15;
    const int m0 = blockIdx.x * 128;
    const int tid = threadIdx.x, lane = tid & 31, w = tid >> 5;
    const int wm = w * 16;

    const float* Ap = attn + ((size_t)bh << 20) + (size_t)m0 * SDIM;
    const __half* vhp = g_vth + (size_t)bh * DDIM * SDIM;
    const __half* vlp = g_vtl + (size_t)bh * DDIM * SDIM;

    unsigned aoH, boH[4], boL[4];
    {
        int ar = lane & 15, ak = (lane >> 4) * 8;
        aoH = s2u(Ah) + ((wm + ar) * LDSS2 + ak) * 2;
        int nr = (lane & 7) + ((lane >> 4) & 1) * 8;
        int nk = ((lane >> 3) & 1) * 8;
#pragma unroll
        for (int np = 0; np < 4; np++) {
            boH[np] = s2u(Bh) + ((np * 16 + nr) * LDSS2 + nk) * 2;
            boL[np] = s2u(Bl) + ((np * 16 + nr) * LDSS2 + nk) * 2;
        }
    }

    float acc[8][4];
#pragma unroll
    for (int i = 0; i < 8; i++)
#pragma unroll
        for (int e = 0; e < 4; e++) acc[i][e] = 0.f;

#pragma unroll 1
    for (int k0 = 0; k0 < SDIM; k0 += 32) {
#pragma unroll
        for (int l = 0; l < 4; l++) {
            int idx = l * 256 + tid;
            int m = idx >> 3, kq = (idx & 7) * 4;
            float4 v = __ldcs((const float4*)&Ap[(size_t)m * SDIM + k0 + kq]);
            int o = m * LDSS2 + kq;
            *(__half2*)&Ah[o]     = __floats2half2_rn(v.x, v.y);
            *(__half2*)&Ah[o + 2] = __floats2half2_rn(v.z, v.w);
        }
        {
            int d = tid >> 2, kq = (tid & 3) * 8;
            uint4 hv = *(const uint4*)&vhp[(size_t)d * SDIM + k0 + kq];
            *(uint4*)&Bh[d * LDSS2 + kq] = hv;
            uint4 lv = *(const uint4*)&vlp[(size_t)d * SDIM + k0 + kq];
            *(uint4*)&Bl[d * LDSS2 + kq] = lv;
        }
        __syncthreads();

#pragma unroll
        for (int ks = 0; ks < 2; ks++) {
            unsigned off = ks * 32;
            unsigned ah[4], bhf[8][2], blf[8][2];
            ldsm4(ah, aoH + off);
#pragma unroll
            for (int np = 0; np < 4; np++) {
                unsigned r[4];
                ldsm4(r, boH[np] + off);
                bhf[2 * np][0] = r[0]; bhf[2 * np][1] = r[1];
                bhf[2 * np + 1][0] = r[2]; bhf[2 * np + 1][1] = r[3];
                ldsm4(r, boL[np] + off);
                blf[2 * np][0] = r[0]; blf[2 * np][1] = r[1];
                blf[2 * np + 1][0] = r[2]; blf[2 * np + 1][1] = r[3];
            }
#pragma unroll
            for (int nt = 0; nt < 8; nt++) {
                mma16816h(acc[nt], ah, bhf[nt]);
                mma16816h(acc[nt], ah, blf[nt]);
            }
        }
        __syncthreads();
    }

    const int g = lane >> 2, cq = (lane & 3) * 2;
#pragma unroll
    for (int nt = 0; nt < 8; nt++) {
        int d = nt * 8 + cq;
        int r0 = m0 + wm + g;
        *(float2*)&g_val[((size_t)(bb * SDIM + r0)) * EDIM + h * DDIM + d] =
            make_float2(acc[nt][0], acc[nt][1]);
        *(float2*)&g_val[((size_t)(bb * SDIM + r0 + 8)) * EDIM + h * DDIM + d] =
            make_float2(acc[nt][2], acc[nt][3]);
    }
}

// ---------------- launch ----------------------------------------------
extern "C" void kernel_launch(void* const* d_in, const int* in_sizes, int n_in,
                              void* d_out, int out_size)
{
    const float* x  = (const float*)d_in[0];
    const float* W0 = (const float*)d_in[1];
    const float* b0 = (const float*)d_in[2];
    const float* W1 = (const float*)d_in[3];
    const float* b1 = (const float*)d_in[4];
    const float* W2 = (const float*)d_in[5];
    const float* b2 = (const float*)d_in[6];
    const float* Wv = (const float*)d_in[7];
    const float* bv = (const float*)d_in[8];
    const float* Wo = (const float*)d_in[9];
    const float* bo = (const float*)d_in[10];
    const float* A  = (const float*)d_in[11];

    float* out  = (float*)d_out;
    float* attn = out + (size_t)MTOT * EDIM;

    xsum_kernel<<<dim3(4, 4), 256>>>(x);
    gemm_proj_kernel<<<dim3(8, 32, 3), 256>>>(x, W0, b0, W1, b1, Wv, bv);

    s2small_kernel<<<dim3(128, 4), 256>>>(W2, b2);
    m_kernel<<<64, 256>>>(A);
    vt_kernel<<<dim3(16, BH), 256>>>();

    lsm_kernel<<<dim3(32, BH), 512>>>(attn);
    av_tc_kernel<<<dim3(8, BH), 256>>>(attn);

    gemm_out_kernel<<<dim3(8, 32), 256>>>(Wo, bo, out);
}

// round 16
// speedup vs baseline: 1.0671x; 1.0671x over previous
#include <cuda_runtime.h>
#include <cuda_bf16.h>
#include <cuda_fp16.h>
#include <math.h>

#define SDIM 1024
#define EDIM 1024
#define BDIM 4
#define HDIM 16
#define DDIM 64
#define BH   64
#define MTOT 4096

typedef __nv_bfloat16  bf16;
typedef __nv_bfloat162 bf162;

// ---------------- scratch (device globals; no allocation) ----------------
__device__ float g_p0[BH * SDIM * DDIM];
__device__ __half g_p1h[BH * SDIM * DDIM], g_p1l[BH * SDIM * DDIM];
__device__ float g_v [BH * SDIM * DDIM];
__device__ float g_s2[BDIM * EDIM];
__device__ float g_M [BH * DDIM * DDIM];
__device__ float g_xsum[BDIM * EDIM];
__device__ float g_val[MTOT * EDIM];
__device__ __half g_vth[BH * DDIM * SDIM], g_vtl[BH * DDIM * SDIM];

// ---------------- helpers -------------------------------------------------
__device__ __forceinline__ unsigned s2u(const void* p) {
    return (unsigned)__cvta_generic_to_shared(p);
}
__device__ __forceinline__ void ldsm4(unsigned* r, unsigned addr) {
    asm volatile("ldmatrix.sync.aligned.m8n8.x4.shared.b16 {%0,%1,%2,%3}, [%4];"
                 : "=r"(r[0]), "=r"(r[1]), "=r"(r[2]), "=r"(r[3]) : "r"(addr));
}
__device__ __forceinline__ void mma16816(float* c, const unsigned* a, const unsigned* b) {
    asm volatile("mma.sync.aligned.m16n8k16.row.col.f32.bf16.bf16.f32 "
                 "{%0,%1,%2,%3}, {%4,%5,%6,%7}, {%8,%9}, {%0,%1,%2,%3};"
                 : "+f"(c[0]), "+f"(c[1]), "+f"(c[2]), "+f"(c[3])
                 : "r"(a[0]), "r"(a[1]), "r"(a[2]), "r"(a[3]), "r"(b[0]), "r"(b[1]));
}
__device__ __forceinline__ void mma16816h(float* c, const unsigned* a, const unsigned* b) {
    asm volatile("mma.sync.aligned.m16n8k16.row.col.f32.f16.f16.f32 "
                 "{%0,%1,%2,%3}, {%4,%5,%6,%7}, {%8,%9}, {%0,%1,%2,%3};"
                 : "+f"(c[0]), "+f"(c[1]), "+f"(c[2]), "+f"(c[3])
                 : "r"(a[0]), "r"(a[1]), "r"(a[2]), "r"(a[3]), "r"(b[0]), "r"(b[1]));
}
__device__ __forceinline__ void h2split(float x, float y, unsigned& hi, unsigned& lo) {
    __half2 h = __floats2half2_rn(x, y);
    float hx = __low2float(h), hy = __high2float(h);
    __half2 l = __floats2half2_rn(x - hx, y - hy);
    hi = *(unsigned*)&h;
    lo = *(unsigned*)&l;
}

// ---------------- xsum[b][e] = sum_s x[b,s,e] -----------------------------
__global__ void xsum_kernel(const float* __restrict__ X)
{
    int b = blockIdx.y;
    int e = blockIdx.x * 256 + threadIdx.x;
    const float* p = X + ((size_t)b * SDIM) * EDIM + e;
    float acc = 0.f;
    for (int s = 0; s < SDIM; s++) acc += p[(size_t)s * EDIM];
    g_xsum[b * EDIM + e] = acc;
}

// ---------------- s2[b*1024+col] = xsum[b] . W2[col] + 1024*b2[col] -------
__global__ void s2small_kernel(const float* __restrict__ W2, const float* __restrict__ b2)
{
    int w = threadIdx.x >> 5, lane = threadIdx.x & 31;
    int b = blockIdx.y;
    int col = blockIdx.x * 8 + w;
    const float* wp = W2 + (size_t)col * EDIM;
    const float* xp = g_xsum + b * EDIM;
    float acc = 0.f;
    for (int e = lane; e < EDIM; e += 32) acc += xp[e] * wp[e];
#pragma unroll
    for (int o = 16; o > 0; o >>= 1) acc += __shfl_xor_sync(0xffffffffu, acc, o);
    if (lane == 0) g_s2[b * EDIM + col] = acc + 1024.0f * b2[col];
}

// ---------------- M[bh,(a,c)] = sum_d A[(a,c),d]*s2[bh,d] -----------------
__global__ void __launch_bounds__(256) m_kernel(const float* __restrict__ A)
{
    __shared__ float s2s[64][68];
    __shared__ float As[64][68];
    const int tid = threadIdx.x;
    const int r0 = blockIdx.x * 64;

    for (int i = tid; i < 1024; i += 256) {
        int r = i >> 4, c4 = (i & 15) * 4;
        float4 v = *(const float4*)&g_s2[(r >> 4) * EDIM + (r & 15) * 64 + c4];
        *(float4*)&s2s[r][c4] = v;
    }
    for (int i = tid; i < 1024; i += 256) {
        int r = i >> 4, c4 = (i & 15) * 4;
        float4 v = *(const float4*)&A[(size_t)(r0 + r) * 64 + c4];
        *(float4*)&As[r][c4] = v;
    }
    __syncthreads();

    const int row = tid & 63, bh0 = (tid >> 6) * 16;
    float acc[16];
#pragma unroll
    for (int j = 0; j < 16; j++) acc[j] = 0.f;
#pragma unroll
    for (int d4 = 0; d4 < 16; d4++) {
        float4 a = *(float4*)&As[row][d4 * 4];
#pragma unroll
        for (int j = 0; j < 16; j++) {
            float4 s = *(float4*)&s2s[bh0 + j][d4 * 4];
            acc[j] += a.x * s.x + a.y * s.y + a.z * s.z + a.w * s.w;
        }
    }
#pragma unroll
    for (int j = 0; j < 16; j++)
        g_M[(size_t)(bh0 + j) * 4096 + r0 + row] = acc[j];
}

// ---------------- proven tensor-core NT GEMM (bf16 split-3) ---------------
// MODE 0: packed head fp32    MODE 1: row-major fp32
// MODE 2: packed head fp16 hi/lo split (for p1)
#define KT    32
#define LDSS  40

template <int MODE>
__device__ __forceinline__ void gemm_core(
    const float* __restrict__ X, const float* __restrict__ W,
    const float* __restrict__ bias, float* __restrict__ Out)
{
    __shared__ bf16 Ah[128 * LDSS];
    __shared__ bf16 Al[128 * LDSS];
    __shared__ bf16 Bh[128 * LDSS];
    __shared__ bf16 Bl[128 * LDSS];

    const int tid  = threadIdx.x;
    const int lane = tid & 31;
    const int wid  = tid >> 5;
    const int m0 = blockIdx.y * 128;
    const int n0 = blockIdx.x * 128;
    const int wm = (wid >> 2) * 64;
    const int wn = (wid & 3) * 32;

    float4 pa[4], pb[4];

    unsigned baA[4], baAl[4], baB[2], baBl[2];
    {
        int ar = lane & 15, ak = (lane >> 4) * 8;
#pragma unroll
        for (int mi = 0; mi < 4; mi++) {
            int off = ((wm + mi * 16 + ar) * LDSS + ak) * 2;
            baA[mi]  = s2u(Ah) + off;
            baAl[mi] = s2u(Al) + off;
        }
        int nr = (lane & 7) + ((lane >> 4) & 1) * 8;
        int nk = ((lane >> 3) & 1) * 8;
#pragma unroll
        for (int np = 0; np < 2; np++) {
            int off = ((wn + np * 16 + nr) * LDSS + nk) * 2;
            baB[np]  = s2u(Bh) + off;
            baBl[np] = s2u(Bl) + off;
        }
    }

    float acc[4][4][4];
#pragma unroll
    for (int i = 0; i < 4; i++)
#pragma unroll
        for (int j = 0; j < 4; j++)
#pragma unroll
            for (int e = 0; e < 4; e++) acc[i][j][e] = 0.f;

    auto loadTile = [&](int k0) {
#pragma unroll
        for (int l = 0; l < 4; l++) {
            int idx = l * 256 + tid;
            int row = idx >> 3, kq = (idx & 7) * 4;
            pa[l] = *(const float4*)&X[(size_t)(m0 + row) * EDIM + k0 + kq];
            pb[l] = *(const float4*)&W[(size_t)(n0 + row) * EDIM + k0 + kq];
        }
    };
    auto storeTile = [&]() {
#pragma unroll
        for (int l = 0; l < 4; l++) {
            int idx = l * 256 + tid;
            int row = idx >> 3, kq = (idx & 7) * 4;
            int o = row * LDSS + kq;
            float4 a = pa[l];
            bf16 hx = __float2bfloat16_rn(a.x);
            bf16 hy = __float2bfloat16_rn(a.y);
            bf16 hz = __float2bfloat16_rn(a.z);
            bf16 hw = __float2bfloat16_rn(a.w);
            *(bf162*)&Ah[o]     = bf162(hx, hy);
            *(bf162*)&Ah[o + 2] = bf162(hz, hw);
            *(bf162*)&Al[o]     = bf162(
                __float2bfloat16_rn(a.x - __bfloat162float(hx)),
                __float2bfloat16_rn(a.y - __bfloat162float(hy)));
            *(bf162*)&Al[o + 2] = bf162(
                __float2bfloat16_rn(a.z - __bfloat162float(hz)),
                __float2bfloat16_rn(a.w - __bfloat162float(hw)));
            float4 b = pb[l];
            hx = __float2bfloat16_rn(b.x); hy = __float2bfloat16_rn(b.y);
            hz = __float2bfloat16_rn(b.z); hw = __float2bfloat16_rn(b.w);
            *(bf162*)&Bh[o]     = bf162(hx, hy);
            *(bf162*)&Bh[o + 2] = bf162(hz, hw);
            *(bf162*)&Bl[o]     = bf162(
                __float2bfloat16_rn(b.x - __bfloat162float(hx)),
                __float2bfloat16_rn(b.y - __bfloat162float(hy)));
            *(bf162*)&Bl[o + 2] = bf162(
                __float2bfloat16_rn(b.z - __bfloat162float(hz)),
                __float2bfloat16_rn(b.w - __bfloat162float(hw)));
        }
    };

    loadTile(0);
    storeTile();
    __syncthreads();

    for (int kt = 0; kt < EDIM / KT; kt++) {
        bool has_next = (kt + 1) < EDIM / KT;
        if (has_next) loadTile((kt + 1) * KT);

#pragma unroll
        for (int kk = 0; kk < 2; kk++) {
            unsigned boff = kk * 32;
            unsigned ah[4][4], al[4][4], bh_[4][2], bl_[4][2];
#pragma unroll
            for (int mi = 0; mi < 4; mi++) ldsm4(ah[mi], baA[mi] + boff);
#pragma unroll
            for (int np = 0; np < 2; np++) {
                unsigned r[4];
                ldsm4(r, baB[np] + boff);
                bh_[2 * np][0] = r[0]; bh_[2 * np][1] = r[1];
                bh_[2 * np + 1][0] = r[2]; bh_[2 * np + 1][1] = r[3];
            }
#pragma unroll
            for (int mi = 0; mi < 4; mi++)
#pragma unroll
                for (int ni = 0; ni < 4; ni++) mma16816(acc[mi][ni], ah[mi], bh_[ni]);

#pragma unroll
            for (int np = 0; np < 2; np++) {
                unsigned r[4];
                ldsm4(r, baBl[np] + boff);
                bl_[2 * np][0] = r[0]; bl_[2 * np][1] = r[1];
                bl_[2 * np + 1][0] = r[2]; bl_[2 * np + 1][1] = r[3];
            }
#pragma unroll
            for (int mi = 0; mi < 4; mi++)
#pragma unroll
                for (int ni = 0; ni < 4; ni++) mma16816(acc[mi][ni], ah[mi], bl_[ni]);

#pragma unroll
            for (int mi = 0; mi < 4; mi++) ldsm4(al[mi], baAl[mi] + boff);
#pragma unroll
            for (int mi = 0; mi < 4; mi++)
#pragma unroll
                for (int ni = 0; ni < 4; ni++) mma16816(acc[mi][ni], al[mi], bh_[ni]);
        }

        __syncthreads();
        if (has_next) {
            storeTile();
            __syncthreads();
        }
    }

    const int g = lane >> 2;
    const int cq = (lane & 3) * 2;
#pragma unroll
    for (int mi = 0; mi < 4; mi++) {
#pragma unroll
        for (int ni = 0; ni < 4; ni++) {
            int col = n0 + wn + ni * 8 + cq;
            float2 bia = *(const float2*)&bias[col];
#pragma unroll
            for (int half = 0; half < 2; half++) {
                int row = m0 + wm + mi * 16 + g + half * 8;
                float v0 = acc[mi][ni][half * 2 + 0] + bia.x;
                float v1 = acc[mi][ni][half * 2 + 1] + bia.y;
                if (MODE == 0) {
                    int bb = row >> 10, ss = row & 1023;
                    int h = col >> 6, d = col & 63;
                    *(float2*)&Out[(((size_t)(bb * HDIM + h) * SDIM) + ss) * DDIM + d]
                        = make_float2(v0, v1);
                } else if (MODE == 1) {
                    *(float2*)&Out[(size_t)row * EDIM + col] = make_float2(v0, v1);
                } else {
                    int bb = row >> 10, ss = row & 1023;
                    int h = col >> 6, d = col & 63;
                    size_t idx = (((size_t)(bb * HDIM + h) * SDIM) + ss) * DDIM + d;
                    unsigned hi, lo;
                    h2split(v0, v1, hi, lo);
                    *(unsigned*)&g_p1h[idx] = hi;
                    *(unsigned*)&g_p1l[idx] = lo;
                }
            }
        }
    }
}

__global__ void __launch_bounds__(256, 1) gemm_proj_kernel(
    const float* __restrict__ X,
    const float* __restrict__ W0, const float* __restrict__ b0,
    const float* __restrict__ W1, const float* __restrict__ b1,
    const float* __restrict__ Wv, const float* __restrict__ bv)
{
    switch (blockIdx.z) {
        case 0:  gemm_core<0>(X, W0, b0, g_p0); break;
        case 1:  gemm_core<2>(X, W1, b1, nullptr); break;
        default: gemm_core<0>(X, Wv, bv, g_v);  break;
    }
}

__global__ void __launch_bounds__(256, 1) gemm_out_kernel(
    const float* __restrict__ Wo, const float* __restrict__ bo, float* __restrict__ Out)
{
    gemm_core<1>(g_val, Wo, bo, Out);
}

// ---- fused t + logits (pre-split fp16 p1, ldmatrix B) + softmax ----------
// 16-row blocks, 256 threads. Inner loop: pure ldmatrix + mma.
// LP = 72 halves (64 data + 8 pad) -> 144B row stride, rows do NOT overlap.
#define PSTR 68
#define LP 72
#define B1_BYTES (128 * LP * 2)   // 18432 per array

__global__ void __launch_bounds__(256) lsm_kernel(float* __restrict__ attn)
{
    __shared__ char sbuf[2 * B1_BYTES];   // B1h | B1l ; prologue aliases for M staging
    __shared__ float As[16 * PSTR];
    __shared__ float wmax[8][16];
    __shared__ float wsum[8][16];

    __half* B1h = (__half*)sbuf;
    __half* B1l = (__half*)(sbuf + B1_BYTES);
    float*  Ms  = (float*)sbuf;           // 64 x PSTR floats = 17408 B (fits in B1h area)

    const int bh = blockIdx.y;
    const int m0 = blockIdx.x * 16;
    const int tid = threadIdx.x, lane = tid & 31, w = tid >> 5;
    const int g = lane >> 2, t4 = lane & 3;

    const __half* P1hp = g_p1h + (size_t)bh * SDIM * DDIM;
    const __half* P1lp = g_p1l + (size_t)bh * SDIM * DDIM;
    float* Op = attn + ((size_t)bh << 20) + (size_t)m0 * SDIM;

    // ---- prologue: t = (p0_tile(16x64) @ M(64x64)) * 0.125 ----
    {
        const float* Mp = g_M + (size_t)bh * 4096;
#pragma unroll
        for (int l = 0; l < 4; l++) {
            int idx = l * 256 + tid;
            int row = idx >> 4, c4 = (idx & 15) * 4;
            *(float4*)&Ms[row * PSTR + c4] = *(const float4*)&Mp[row * 64 + c4];
        }
        const float* P0p = g_p0 + ((size_t)bh * SDIM + m0) * DDIM;
        int r = tid >> 4, f4 = (tid & 15) * 4;
        *(float4*)&As[r * PSTR + f4] = *(const float4*)&P0p[r * 64 + f4];
    }
    __syncthreads();
    {
        int r = tid >> 4, c4 = (tid & 15) * 4;
        float4 tacc = make_float4(0.f, 0.f, 0.f, 0.f);
#pragma unroll 8
        for (int a = 0; a < 64; a++) {
            float pa = As[r * PSTR + a];
            float4 m = *(float4*)&Ms[a * PSTR + c4];
            tacc.x += pa * m.x; tacc.y += pa * m.y;
            tacc.z += pa * m.z; tacc.w += pa * m.w;
        }
        __syncthreads();
        tacc.x *= 0.125f; tacc.y *= 0.125f; tacc.z *= 0.125f; tacc.w *= 0.125f;
        *(float4*)&As[r * PSTR + c4] = tacc;
    }
    __syncthreads();

    // precompute fp16 hi/lo A-fragments for the 4 k16-steps
    unsigned ahi[4][4], alo[4][4];
#pragma unroll
    for (int ks = 0; ks < 4; ks++) {
        int c0 = ks * 16 + 2 * t4;
        float2 x0 = *(float2*)&As[g * PSTR + c0];
        float2 x1 = *(float2*)&As[(g + 8) * PSTR + c0];
        float2 x2 = *(float2*)&As[g * PSTR + c0 + 8];
        float2 x3 = *(float2*)&As[(g + 8) * PSTR + c0 + 8];
        h2split(x0.x, x0.y, ahi[ks][0], alo[ks][0]);
        h2split(x1.x, x1.y, ahi[ks][1], alo[ks][1]);
        h2split(x2.x, x2.y, ahi[ks][2], alo[ks][2]);
        h2split(x3.x, x3.y, ahi[ks][3], alo[ks][3]);
    }

    // ldmatrix B-fragment base addresses (this warp's 16 n-rows)
    unsigned boH, boL;
    {
        int nr = (lane & 7) + ((lane >> 4) & 1) * 8;
        int nk = ((lane >> 3) & 1) * 8;
        boH = s2u(B1h) + ((w * 16 + nr) * LP + nk) * 2;
        boL = s2u(B1l) + ((w * 16 + nr) * LP + nk) * 2;
    }

    float acc[8][2][4];
#pragma unroll
    for (int c = 0; c < 8; c++)
#pragma unroll
        for (int nt = 0; nt < 2; nt++)
#pragma unroll
            for (int e = 0; e < 4; e++) acc[c][nt][e] = 0.f;

#pragma unroll 1
    for (int c = 0; c < 8; c++) {
        __syncthreads();
#pragma unroll
        for (int l = 0; l < 4; l++) {
            int idx = l * 256 + tid;
            int row = idx >> 3, u = (idx & 7) * 8;
            *(uint4*)&B1h[row * LP + u] =
                *(const uint4*)&P1hp[(size_t)(c * 128 + row) * 64 + u];
            *(uint4*)&B1l[row * LP + u] =
                *(const uint4*)&P1lp[(size_t)(c * 128 + row) * 64 + u];
        }
        __syncthreads();

#pragma unroll
        for (int ks = 0; ks < 4; ks++) {
            unsigned rh[4], rl[4];
            ldsm4(rh, boH + ks * 32);
            ldsm4(rl, boL + ks * 32);
            mma16816h(acc[c][0], ahi[ks], rh);
            mma16816h(acc[c][0], ahi[ks], rl);
            mma16816h(acc[c][0], alo[ks], rh);
            mma16816h(acc[c][1], ahi[ks], rh + 2);
            mma16816h(acc[c][1], ahi[ks], rl + 2);
            mma16816h(acc[c][1], alo[ks], rh + 2);
        }
    }

    // ---- softmax over full rows (logits already scaled) ----
    float mr0 = -1e30f, mr1 = -1e30f;
#pragma unroll
    for (int c = 0; c < 8; c++)
#pragma unroll
        for (int nt = 0; nt < 2; nt++) {
            mr0 = fmaxf(mr0, fmaxf(acc[c][nt][0], acc[c][nt][1]));
            mr1 = fmaxf(mr1, fmaxf(acc[c][nt][2], acc[c][nt][3]));
        }
#pragma unroll
    for (int o = 1; o <= 2; o <<= 1) {
        mr0 = fmaxf(mr0, __shfl_xor_sync(0xffffffffu, mr0, o));
        mr1 = fmaxf(mr1, __shfl_xor_sync(0xffffffffu, mr1, o));
    }
    if (t4 == 0) { wmax[w][g] = mr0; wmax[w][g + 8] = mr1; }
    __syncthreads();
    float M0 = -1e30f, M1 = -1e30f;
#pragma unroll
    for (int ww = 0; ww < 8; ww++) {
        M0 = fmaxf(M0, wmax[ww][g]);
        M1 = fmaxf(M1, wmax[ww][g + 8]);
    }

    float s0 = 0.f, s1 = 0.f;
#pragma unroll
    for (int c = 0; c < 8; c++)
#pragma unroll
        for (int nt = 0; nt < 2; nt++) {
            float e0 = __expf(acc[c][nt][0] - M0);
            float e1 = __expf(acc[c][nt][1] - M0);
            float e2 = __expf(acc[c][nt][2] - M1);
            float e3 = __expf(acc[c][nt][3] - M1);
            acc[c][nt][0] = e0; acc[c][nt][1] = e1;
            acc[c][nt][2] = e2; acc[c][nt][3] = e3;
            s0 += e0 + e1; s1 += e2 + e3;
        }
#pragma unroll
    for (int o = 1; o <= 2; o <<= 1) {
        s0 += __shfl_xor_sync(0xffffffffu, s0, o);
        s1 += __shfl_xor_sync(0xffffffffu, s1, o);
    }
    if (t4 == 0) { wsum[w][g] = s0; wsum[w][g + 8] = s1; }
    __syncthreads();
    float S0 = 0.f, S1 = 0.f;
#pragma unroll
    for (int ww = 0; ww < 8; ww++) { S0 += wsum[ww][g]; S1 += wsum[ww][g + 8]; }
    float inv0 = 1.0f / S0, inv1 = 1.0f / S1;

#pragma unroll
    for (int c = 0; c < 8; c++)
#pragma unroll
        for (int nt = 0; nt < 2; nt++) {
            int col = c * 128 + w * 16 + nt * 8 + 2 * t4;
            __stcs((float2*)&Op[(size_t)g * SDIM + col],
                   make_float2(acc[c][nt][0] * inv0, acc[c][nt][1] * inv0));
            __stcs((float2*)&Op[(size_t)(g + 8) * SDIM + col],
                   make_float2(acc[c][nt][2] * inv1, acc[c][nt][3] * inv1));
        }
}

// ---------------- V transpose + fp16 split: vT[bh][d][s] ------------------
__global__ void vt_kernel()
{
    __shared__ float ts[64][65];
    int bh = blockIdx.y;
    int s0 = blockIdx.x * 64;
    int tid = threadIdx.x;
#pragma unroll
    for (int l = 0; l < 4; l++) {
        int idx = l * 256 + tid;
        int s = idx >> 4, f4 = idx & 15;
        float4 v = *(const float4*)&g_v[((size_t)bh * SDIM + s0 + s) * DDIM + f4 * 4];
        ts[s][f4 * 4 + 0] = v.x; ts[s][f4 * 4 + 1] = v.y;
        ts[s][f4 * 4 + 2] = v.z; ts[s][f4 * 4 + 3] = v.w;
    }
    __syncthreads();
#pragma unroll
    for (int l = 0; l < 4; l++) {
        int idx = l * 256 + tid;
        int d = idx >> 4, sg = (idx & 15) * 4;
        float x0 = ts[sg + 0][d], x1 = ts[sg + 1][d];
        float x2 = ts[sg + 2][d], x3 = ts[sg + 3][d];
        __half h0 = __float2half_rn(x0), h1 = __float2half_rn(x1);
        __half h2 = __float2half_rn(x2), h3 = __float2half_rn(x3);
        size_t o = ((size_t)bh * DDIM + d) * SDIM + s0 + sg;
        *(__half2*)&g_vth[o]     = __half2(h0, h1);
        *(__half2*)&g_vth[o + 2] = __half2(h2, h3);
        *(__half2*)&g_vtl[o] = __half2(__float2half_rn(x0 - __half2float(h0)),
                                       __float2half_rn(x1 - __half2float(h1)));
        *(__half2*)&g_vtl[o + 2] = __half2(__float2half_rn(x2 - __half2float(h2)),
                                           __float2half_rn(x3 - __half2float(h3)));
    }
}

// ---------------- AV: values = attn @ V, fp16 2-term TC -------------------
#define LDSS2 40
__global__ void __launch_bounds__(256, 1) av_tc_kernel(const float* __restrict__ attn)
{
    __shared__ __half Ah[128 * LDSS2];
    __shared__ __half Bh[64 * LDSS2];
    __shared__ __half Bl[64 * LDSS2];

    const int bh = blockIdx.y;
    const int bb = bh >> 4, h = bh & 15;
    const int m0 = blockIdx.x * 128;
    const int tid = threadIdx.x, lane = tid & 31, w = tid >> 5;
    const int wm = w * 16;

    const float* Ap = attn + ((size_t)bh << 20) + (size_t)m0 * SDIM;
    const __half* vhp = g_vth + (size_t)bh * DDIM * SDIM;
    const __half* vlp = g_vtl + (size_t)bh * DDIM * SDIM;

    unsigned aoH, boH[4], boL[4];
    {
        int ar = lane & 15, ak = (lane >> 4) * 8;
        aoH = s2u(Ah) + ((wm + ar) * LDSS2 + ak) * 2;
        int nr = (lane & 7) + ((lane >> 4) & 1) * 8;
        int nk = ((lane >> 3) & 1) * 8;
#pragma unroll
        for (int np = 0; np < 4; np++) {
            boH[np] = s2u(Bh) + ((np * 16 + nr) * LDSS2 + nk) * 2;
            boL[np] = s2u(Bl) + ((np * 16 + nr) * LDSS2 + nk) * 2;
        }
    }

    float acc[8][4];
#pragma unroll
    for (int i = 0; i < 8; i++)
#pragma unroll
        for (int e = 0; e < 4; e++) acc[i][e] = 0.f;

#pragma unroll 1
    for (int k0 = 0; k0 < SDIM; k0 += 32) {
#pragma unroll
        for (int l = 0; l < 4; l++) {
            int idx = l * 256 + tid;
            int m = idx >> 3, kq = (idx & 7) * 4;
            float4 v = __ldcs((const float4*)&Ap[(size_t)m * SDIM + k0 + kq]);
            int o = m * LDSS2 + kq;
            *(__half2*)&Ah[o]     = __floats2half2_rn(v.x, v.y);
            *(__half2*)&Ah[o + 2] = __floats2half2_rn(v.z, v.w);
        }
        {
            int d = tid >> 2, kq = (tid & 3) * 8;
            uint4 hv = *(const uint4*)&vhp[(size_t)d * SDIM + k0 + kq];
            *(uint4*)&Bh[d * LDSS2 + kq] = hv;
            uint4 lv = *(const uint4*)&vlp[(size_t)d * SDIM + k0 + kq];
            *(uint4*)&Bl[d * LDSS2 + kq] = lv;
        }
        __syncthreads();

#pragma unroll
        for (int ks = 0; ks < 2; ks++) {
            unsigned off = ks * 32;
            unsigned ah[4], bhf[8][2], blf[8][2];
            ldsm4(ah, aoH + off);
#pragma unroll
            for (int np = 0; np < 4; np++) {
                unsigned r[4];
                ldsm4(r, boH[np] + off);
                bhf[2 * np][0] = r[0]; bhf[2 * np][1] = r[1];
                bhf[2 * np + 1][0] = r[2]; bhf[2 * np + 1][1] = r[3];
                ldsm4(r, boL[np] + off);
                blf[2 * np][0] = r[0]; blf[2 * np][1] = r[1];
                blf[2 * np + 1][0] = r[2]; blf[2 * np + 1][1] = r[3];
            }
#pragma unroll
            for (int nt = 0; nt < 8; nt++) {
                mma16816h(acc[nt], ah, bhf[nt]);
                mma16816h(acc[nt], ah, blf[nt]);
            }
        }
        __syncthreads();
    }

    const int g = lane >> 2, cq = (lane & 3) * 2;
#pragma unroll
    for (int nt = 0; nt < 8; nt++) {
        int d = nt * 8 + cq;
        int r0 = m0 + wm + g;
        *(float2*)&g_val[((size_t)(bb * SDIM + r0)) * EDIM + h * DDIM + d] =
            make_float2(acc[nt][0], acc[nt][1]);
        *(float2*)&g_val[((size_t)(bb * SDIM + r0 + 8)) * EDIM + h * DDIM + d] =
            make_float2(acc[nt][2], acc[nt][3]);
    }
}

// ---------------- launch ----------------------------------------------
extern "C" void kernel_launch(void* const* d_in, const int* in_sizes, int n_in,
                              void* d_out, int out_size)
{
    const float* x  = (const float*)d_in[0];
    const float* W0 = (const float*)d_in[1];
    const float* b0 = (const float*)d_in[2];
    const float* W1 = (const float*)d_in[3];
    const float* b1 = (const float*)d_in[4];
    const float* W2 = (const float*)d_in[5];
    const float* b2 = (const float*)d_in[6];
    const float* Wv = (const float*)d_in[7];
    const float* bv = (const float*)d_in[8];
    const float* Wo = (const float*)d_in[9];
    const float* bo = (const float*)d_in[10];
    const float* A  = (const float*)d_in[11];

    float* out  = (float*)d_out;
    float* attn = out + (size_t)MTOT * EDIM;

    xsum_kernel<<<dim3(4, 4), 256>>>(x);
    gemm_proj_kernel<<<dim3(8, 32, 3), 256>>>(x, W0, b0, W1, b1, Wv, bv);

    s2small_kernel<<<dim3(128, 4), 256>>>(W2, b2);
    m_kernel<<<64, 256>>>(A);
    vt_kernel<<<dim3(16, BH), 256>>>();

    lsm_kernel<<<dim3(64, BH), 256>>>(attn);
    av_tc_kernel<<<dim3(8, BH), 256>>>(attn);

    gemm_out_kernel<<<dim3(8, 32), 256>>>(Wo, bo, out);
}

// round 17
// speedup vs baseline: 1.0740x; 1.0064x over previous
#include <cuda_runtime.h>
#include <cuda_bf16.h>
#include <cuda_fp16.h>
#include <math.h>

#define SDIM 1024
#define EDIM 1024
#define BDIM 4
#define HDIM 16
#define DDIM 64
#define BH   64
#define MTOT 4096

typedef __nv_bfloat16  bf16;
typedef __nv_bfloat162 bf162;

// ---------------- scratch (device globals; no allocation) ----------------
__device__ float g_p0[BH * SDIM * DDIM];
__device__ __half g_p1h[BH * SDIM * DDIM], g_p1l[BH * SDIM * DDIM];
__device__ float g_v [BH * SDIM * DDIM];
__device__ float g_s2[BDIM * EDIM];
__device__ float g_M [BH * DDIM * DDIM];
__device__ float g_xsum[BDIM * EDIM];
__device__ float g_val[MTOT * EDIM];
__device__ __half g_vth[BH * DDIM * SDIM], g_vtl[BH * DDIM * SDIM];

// ---------------- helpers -------------------------------------------------
__device__ __forceinline__ unsigned s2u(const void* p) {
    return (unsigned)__cvta_generic_to_shared(p);
}
__device__ __forceinline__ void ldsm4(unsigned* r, unsigned addr) {
    asm volatile("ldmatrix.sync.aligned.m8n8.x4.shared.b16 {%0,%1,%2,%3}, [%4];"
                 : "=r"(r[0]), "=r"(r[1]), "=r"(r[2]), "=r"(r[3]) : "r"(addr));
}
__device__ __forceinline__ void mma16816(float* c, const unsigned* a, const unsigned* b) {
    asm volatile("mma.sync.aligned.m16n8k16.row.col.f32.bf16.bf16.f32 "
                 "{%0,%1,%2,%3}, {%4,%5,%6,%7}, {%8,%9}, {%0,%1,%2,%3};"
                 : "+f"(c[0]), "+f"(c[1]), "+f"(c[2]), "+f"(c[3])
                 : "r"(a[0]), "r"(a[1]), "r"(a[2]), "r"(a[3]), "r"(b[0]), "r"(b[1]));
}
__device__ __forceinline__ void mma16816h(float* c, const unsigned* a, const unsigned* b) {
    asm volatile("mma.sync.aligned.m16n8k16.row.col.f32.f16.f16.f32 "
                 "{%0,%1,%2,%3}, {%4,%5,%6,%7}, {%8,%9}, {%0,%1,%2,%3};"
                 : "+f"(c[0]), "+f"(c[1]), "+f"(c[2]), "+f"(c[3])
                 : "r"(a[0]), "r"(a[1]), "r"(a[2]), "r"(a[3]), "r"(b[0]), "r"(b[1]));
}
__device__ __forceinline__ void h2split(float x, float y, unsigned& hi, unsigned& lo) {
    __half2 h = __floats2half2_rn(x, y);
    float hx = __low2float(h), hy = __high2float(h);
    __half2 l = __floats2half2_rn(x - hx, y - hy);
    hi = *(unsigned*)&h;
    lo = *(unsigned*)&l;
}

// ---------------- xsum[b][e] = sum_s x[b,s,e] -----------------------------
__global__ void xsum_kernel(const float* __restrict__ X)
{
    int b = blockIdx.y;
    int e = blockIdx.x * 256 + threadIdx.x;
    const float* p = X + ((size_t)b * SDIM) * EDIM + e;
    float acc = 0.f;
    for (int s = 0; s < SDIM; s++) acc += p[(size_t)s * EDIM];
    g_xsum[b * EDIM + e] = acc;
}

// ---------------- s2[b*1024+col] = xsum[b] . W2[col] + 1024*b2[col] -------
__global__ void s2small_kernel(const float* __restrict__ W2, const float* __restrict__ b2)
{
    int w = threadIdx.x >> 5, lane = threadIdx.x & 31;
    int b = blockIdx.y;
    int col = blockIdx.x * 8 + w;
    const float* wp = W2 + (size_t)col * EDIM;
    const float* xp = g_xsum + b * EDIM;
    float acc = 0.f;
    for (int e = lane; e < EDIM; e += 32) acc += xp[e] * wp[e];
#pragma unroll
    for (int o = 16; o > 0; o >>= 1) acc += __shfl_xor_sync(0xffffffffu, acc, o);
    if (lane == 0) g_s2[b * EDIM + col] = acc + 1024.0f * b2[col];
}

// ---------------- M[bh,(a,c)] = sum_d A[(a,c),d]*s2[bh,d] -----------------
__global__ void __launch_bounds__(256) m_kernel(const float* __restrict__ A)
{
    __shared__ float s2s[64][68];
    __shared__ float As[64][68];
    const int tid = threadIdx.x;
    const int r0 = blockIdx.x * 64;

    for (int i = tid; i < 1024; i += 256) {
        int r = i >> 4, c4 = (i & 15) * 4;
        float4 v = *(const float4*)&g_s2[(r >> 4) * EDIM + (r & 15) * 64 + c4];
        *(float4*)&s2s[r][c4] = v;
    }
    for (int i = tid; i < 1024; i += 256) {
        int r = i >> 4, c4 = (i & 15) * 4;
        float4 v = *(const float4*)&A[(size_t)(r0 + r) * 64 + c4];
        *(float4*)&As[r][c4] = v;
    }
    __syncthreads();

    const int row = tid & 63, bh0 = (tid >> 6) * 16;
    float acc[16];
#pragma unroll
    for (int j = 0; j < 16; j++) acc[j] = 0.f;
#pragma unroll
    for (int d4 = 0; d4 < 16; d4++) {
        float4 a = *(float4*)&As[row][d4 * 4];
#pragma unroll
        for (int j = 0; j < 16; j++) {
            float4 s = *(float4*)&s2s[bh0 + j][d4 * 4];
            acc[j] += a.x * s.x + a.y * s.y + a.z * s.z + a.w * s.w;
        }
    }
#pragma unroll
    for (int j = 0; j < 16; j++)
        g_M[(size_t)(bh0 + j) * 4096 + r0 + row] = acc[j];
}

// ------- tensor-core NT GEMM (bf16 split-3, double-buffered smem) ---------
// MODE 0: packed head fp32   MODE 1: row-major fp32
// MODE 2: packed head fp16 hi/lo split (for p1)
#define KT    32
#define LDSS  40
#define ARRB  (128 * LDSS * 2)    // 10240 bytes per array
#define STGB  (4 * ARRB)          // 40960 bytes per stage
#define GSMB  (2 * STGB)          // 81920 bytes dynamic smem

template <int MODE>
__device__ __forceinline__ void gemm_core(
    const float* __restrict__ X, const float* __restrict__ W,
    const float* __restrict__ bias, float* __restrict__ Out)
{
    extern __shared__ char gsm[];
    const unsigned sb0 = s2u(gsm);

    const int tid  = threadIdx.x;
    const int lane = tid & 31;
    const int wid  = tid >> 5;
    const int m0 = blockIdx.y * 128;
    const int n0 = blockIdx.x * 128;
    const int wm = (wid >> 2) * 64;
    const int wn = (wid & 3) * 32;

    float4 pa[4], pb[4];

    // ldmatrix element offsets within a stage (bytes)
    unsigned baA[4], baB[2];
    {
        int ar = lane & 15, ak = (lane >> 4) * 8;
#pragma unroll
        for (int mi = 0; mi < 4; mi++)
            baA[mi] = ((wm + mi * 16 + ar) * LDSS + ak) * 2;
        int nr = (lane & 7) + ((lane >> 4) & 1) * 8;
        int nk = ((lane >> 3) & 1) * 8;
#pragma unroll
        for (int np = 0; np < 2; np++)
            baB[np] = ((wn + np * 16 + nr) * LDSS + nk) * 2;
    }

    float acc[4][4][4];
#pragma unroll
    for (int i = 0; i < 4; i++)
#pragma unroll
        for (int j = 0; j < 4; j++)
#pragma unroll
            for (int e = 0; e < 4; e++) acc[i][j][e] = 0.f;

    auto loadTile = [&](int k0) {
#pragma unroll
        for (int l = 0; l < 4; l++) {
            int idx = l * 256 + tid;
            int row = idx >> 3, kq = (idx & 7) * 4;
            pa[l] = *(const float4*)&X[(size_t)(m0 + row) * EDIM + k0 + kq];
            pb[l] = *(const float4*)&W[(size_t)(n0 + row) * EDIM + k0 + kq];
        }
    };
    auto storeTile = [&](int st) {
        bf16* Ah = (bf16*)(gsm + st * STGB);
        bf16* Al = (bf16*)(gsm + st * STGB + ARRB);
        bf16* Bh = (bf16*)(gsm + st * STGB + 2 * ARRB);
        bf16* Bl = (bf16*)(gsm + st * STGB + 3 * ARRB);
#pragma unroll
        for (int l = 0; l < 4; l++) {
            int idx = l * 256 + tid;
            int row = idx >> 3, kq = (idx & 7) * 4;
            int o = row * LDSS + kq;
            float4 a = pa[l];
            bf16 hx = __float2bfloat16_rn(a.x);
            bf16 hy = __float2bfloat16_rn(a.y);
            bf16 hz = __float2bfloat16_rn(a.z);
            bf16 hw = __float2bfloat16_rn(a.w);
            *(bf162*)&Ah[o]     = bf162(hx, hy);
            *(bf162*)&Ah[o + 2] = bf162(hz, hw);
            *(bf162*)&Al[o]     = bf162(
                __float2bfloat16_rn(a.x - __bfloat162float(hx)),
                __float2bfloat16_rn(a.y - __bfloat162float(hy)));
            *(bf162*)&Al[o + 2] = bf162(
                __float2bfloat16_rn(a.z - __bfloat162float(hz)),
                __float2bfloat16_rn(a.w - __bfloat162float(hw)));
            float4 b = pb[l];
            hx = __float2bfloat16_rn(b.x); hy = __float2bfloat16_rn(b.y);
            hz = __float2bfloat16_rn(b.z); hw = __float2bfloat16_rn(b.w);
            *(bf162*)&Bh[o]     = bf162(hx, hy);
            *(bf162*)&Bh[o + 2] = bf162(hz, hw);
            *(bf162*)&Bl[o]     = bf162(
                __float2bfloat16_rn(b.x - __bfloat162float(hx)),
                __float2bfloat16_rn(b.y - __bfloat162float(hy)));
            *(bf162*)&Bl[o + 2] = bf162(
                __float2bfloat16_rn(b.z - __bfloat162float(hz)),
                __float2bfloat16_rn(b.w - __bfloat162float(hw)));
        }
    };

    const int NT = EDIM / KT;
    loadTile(0);
    storeTile(0);
    __syncthreads();

    for (int kt = 0; kt < NT; kt++) {
        bool has_next = (kt + 1) < NT;
        if (has_next) loadTile((kt + 1) * KT);

        // mma on current stage
        unsigned sbase = sb0 + (kt & 1) * STGB;
#pragma unroll
        for (int kk = 0; kk < 2; kk++) {
            unsigned boff = kk * 32;
            unsigned ah[4][4], al[4][4], bh_[4][2], bl_[4][2];
#pragma unroll
            for (int mi = 0; mi < 4; mi++) ldsm4(ah[mi], sbase + baA[mi] + boff);
#pragma unroll
            for (int np = 0; np < 2; np++) {
                unsigned r[4];
                ldsm4(r, sbase + 2 * ARRB + baB[np] + boff);
                bh_[2 * np][0] = r[0]; bh_[2 * np][1] = r[1];
                bh_[2 * np + 1][0] = r[2]; bh_[2 * np + 1][1] = r[3];
            }
#pragma unroll
            for (int mi = 0; mi < 4; mi++)
#pragma unroll
                for (int ni = 0; ni < 4; ni++) mma16816(acc[mi][ni], ah[mi], bh_[ni]);

#pragma unroll
            for (int np = 0; np < 2; np++) {
                unsigned r[4];
                ldsm4(r, sbase + 3 * ARRB + baB[np] + boff);
                bl_[2 * np][0] = r[0]; bl_[2 * np][1] = r[1];
                bl_[2 * np + 1][0] = r[2]; bl_[2 * np + 1][1] = r[3];
            }
#pragma unroll
            for (int mi = 0; mi < 4; mi++)
#pragma unroll
                for (int ni = 0; ni < 4; ni++) mma16816(acc[mi][ni], ah[mi], bl_[ni]);

#pragma unroll
            for (int mi = 0; mi < 4; mi++) ldsm4(al[mi], sbase + ARRB + baA[mi] + boff);
#pragma unroll
            for (int mi = 0; mi < 4; mi++)
#pragma unroll
                for (int ni = 0; ni < 4; ni++) mma16816(acc[mi][ni], al[mi], bh_[ni]);
        }

        // convert next tile into the other stage (overlaps other warps' mma)
        if (has_next) storeTile((kt + 1) & 1);
        __syncthreads();
    }

    const int g = lane >> 2;
    const int cq = (lane & 3) * 2;
#pragma unroll
    for (int mi = 0; mi < 4; mi++) {
#pragma unroll
        for (int ni = 0; ni < 4; ni++) {
            int col = n0 + wn + ni * 8 + cq;
            float2 bia = *(const float2*)&bias[col];
#pragma unroll
            for (int half = 0; half < 2; half++) {
                int row = m0 + wm + mi * 16 + g + half * 8;
                float v0 = acc[mi][ni][half * 2 + 0] + bia.x;
                float v1 = acc[mi][ni][half * 2 + 1] + bia.y;
                if (MODE == 0) {
                    int bb = row >> 10, ss = row & 1023;
                    int h = col >> 6, d = col & 63;
                    *(float2*)&Out[(((size_t)(bb * HDIM + h) * SDIM) + ss) * DDIM + d]
                        = make_float2(v0, v1);
                } else if (MODE == 1) {
                    *(float2*)&Out[(size_t)row * EDIM + col] = make_float2(v0, v1);
                } else {
                    int bb = row >> 10, ss = row & 1023;
                    int h = col >> 6, d = col & 63;
                    size_t idx = (((size_t)(bb * HDIM + h) * SDIM) + ss) * DDIM + d;
                    unsigned hi, lo;
                    h2split(v0, v1, hi, lo);
                    *(unsigned*)&g_p1h[idx] = hi;
                    *(unsigned*)&g_p1l[idx] = lo;
                }
            }
        }
    }
}

__global__ void __launch_bounds__(256, 1) gemm_proj_kernel(
    const float* __restrict__ X,
    const float* __restrict__ W0, const float* __restrict__ b0,
    const float* __restrict__ W1, const float* __restrict__ b1,
    const float* __restrict__ Wv, const float* __restrict__ bv)
{
    switch (blockIdx.z) {
        case 0:  gemm_core<0>(X, W0, b0, g_p0); break;
        case 1:  gemm_core<2>(X, W1, b1, nullptr); break;
        default: gemm_core<0>(X, Wv, bv, g_v);  break;
    }
}

__global__ void __launch_bounds__(256, 1) gemm_out_kernel(
    const float* __restrict__ Wo, const float* __restrict__ bo, float* __restrict__ Out)
{
    gemm_core<1>(g_val, Wo, bo, Out);
}

// ---- fused t + logits (pre-split fp16 p1, ldmatrix B) + softmax ----------
#define PSTR 68
#define LP 72
#define B1_BYTES (128 * LP * 2)   // 18432 per array

__global__ void __launch_bounds__(256) lsm_kernel(float* __restrict__ attn)
{
    __shared__ char sbuf[2 * B1_BYTES];   // B1h | B1l ; prologue aliases for M staging
    __shared__ float As[16 * PSTR];
    __shared__ float wmax[8][16];
    __shared__ float wsum[8][16];

    __half* B1h = (__half*)sbuf;
    __half* B1l = (__half*)(sbuf + B1_BYTES);
    float*  Ms  = (float*)sbuf;           // 64 x PSTR floats = 17408 B (fits in B1h area)

    const int bh = blockIdx.y;
    const int m0 = blockIdx.x * 16;
    const int tid = threadIdx.x, lane = tid & 31, w = tid >> 5;
    const int g = lane >> 2, t4 = lane & 3;

    const __half* P1hp = g_p1h + (size_t)bh * SDIM * DDIM;
    const __half* P1lp = g_p1l + (size_t)bh * SDIM * DDIM;
    float* Op = attn + ((size_t)bh << 20) + (size_t)m0 * SDIM;

    // ---- prologue: t = (p0_tile(16x64) @ M(64x64)) * 0.125 ----
    {
        const float* Mp = g_M + (size_t)bh * 4096;
#pragma unroll
        for (int l = 0; l < 4; l++) {
            int idx = l * 256 + tid;
            int row = idx >> 4, c4 = (idx & 15) * 4;
            *(float4*)&Ms[row * PSTR + c4] = *(const float4*)&Mp[row * 64 + c4];
        }
        const float* P0p = g_p0 + ((size_t)bh * SDIM + m0) * DDIM;
        int r = tid >> 4, f4 = (tid & 15) * 4;
        *(float4*)&As[r * PSTR + f4] = *(const float4*)&P0p[r * 64 + f4];
    }
    __syncthreads();
    {
        int r = tid >> 4, c4 = (tid & 15) * 4;
        float4 tacc = make_float4(0.f, 0.f, 0.f, 0.f);
#pragma unroll 8
        for (int a = 0; a < 64; a++) {
            float pa = As[r * PSTR + a];
            float4 m = *(float4*)&Ms[a * PSTR + c4];
            tacc.x += pa * m.x; tacc.y += pa * m.y;
            tacc.z += pa * m.z; tacc.w += pa * m.w;
        }
        __syncthreads();
        tacc.x *= 0.125f; tacc.y *= 0.125f; tacc.z *= 0.125f; tacc.w *= 0.125f;
        *(float4*)&As[r * PSTR + c4] = tacc;
    }
    __syncthreads();

    unsigned ahi[4][4], alo[4][4];
#pragma unroll
    for (int ks = 0; ks < 4; ks++) {
        int c0 = ks * 16 + 2 * t4;
        float2 x0 = *(float2*)&As[g * PSTR + c0];
        float2 x1 = *(float2*)&As[(g + 8) * PSTR + c0];
        float2 x2 = *(float2*)&As[g * PSTR + c0 + 8];
        float2 x3 = *(float2*)&As[(g + 8) * PSTR + c0 + 8];
        h2split(x0.x, x0.y, ahi[ks][0], alo[ks][0]);
        h2split(x1.x, x1.y, ahi[ks][1], alo[ks][1]);
        h2split(x2.x, x2.y, ahi[ks][2], alo[ks][2]);
        h2split(x3.x, x3.y, ahi[ks][3], alo[ks][3]);
    }

    unsigned boH, boL;
    {
        int nr = (lane & 7) + ((lane >> 4) & 1) * 8;
        int nk = ((lane >> 3) & 1) * 8;
        boH = s2u(B1h) + ((w * 16 + nr) * LP + nk) * 2;
        boL = s2u(B1l) + ((w * 16 + nr) * LP + nk) * 2;
    }

    float acc[8][2][4];
#pragma unroll
    for (int c = 0; c < 8; c++)
#pragma unroll
        for (int nt = 0; nt < 2; nt++)
#pragma unroll
            for (int e = 0; e < 4; e++) acc[c][nt][e] = 0.f;

#pragma unroll 1
    for (int c = 0; c < 8; c++) {
        __syncthreads();
#pragma unroll
        for (int l = 0; l < 4; l++) {
            int idx = l * 256 + tid;
            int row = idx >> 3, u = (idx & 7) * 8;
            *(uint4*)&B1h[row * LP + u] =
                *(const uint4*)&P1hp[(size_t)(c * 128 + row) * 64 + u];
            *(uint4*)&B1l[row * LP + u] =
                *(const uint4*)&P1lp[(size_t)(c * 128 + row) * 64 + u];
        }
        __syncthreads();

#pragma unroll
        for (int ks = 0; ks < 4; ks++) {
            unsigned rh[4], rl[4];
            ldsm4(rh, boH + ks * 32);
            ldsm4(rl, boL + ks * 32);
            mma16816h(acc[c][0], ahi[ks], rh);
            mma16816h(acc[c][0], ahi[ks], rl);
            mma16816h(acc[c][0], alo[ks], rh);
            mma16816h(acc[c][1], ahi[ks], rh + 2);
            mma16816h(acc[c][1], ahi[ks], rl + 2);
            mma16816h(acc[c][1], alo[ks], rh + 2);
        }
    }

    float mr0 = -1e30f, mr1 = -1e30f;
#pragma unroll
    for (int c = 0; c < 8; c++)
#pragma unroll
        for (int nt = 0; nt < 2; nt++) {
            mr0 = fmaxf(mr0, fmaxf(acc[c][nt][0], acc[c][nt][1]));
            mr1 = fmaxf(mr1, fmaxf(acc[c][nt][2], acc[c][nt][3]));
        }
#pragma unroll
    for (int o = 1; o <= 2; o <<= 1) {
        mr0 = fmaxf(mr0, __shfl_xor_sync(0xffffffffu, mr0, o));
        mr1 = fmaxf(mr1, __shfl_xor_sync(0xffffffffu, mr1, o));
    }
    if (t4 == 0) { wmax[w][g] = mr0; wmax[w][g + 8] = mr1; }
    __syncthreads();
    float M0 = -1e30f, M1 = -1e30f;
#pragma unroll
    for (int ww = 0; ww < 8; ww++) {
        M0 = fmaxf(M0, wmax[ww][g]);
        M1 = fmaxf(M1, wmax[ww][g + 8]);
    }

    float s0 = 0.f, s1 = 0.f;
#pragma unroll
    for (int c = 0; c < 8; c++)
#pragma unroll
        for (int nt = 0; nt < 2; nt++) {
            float e0 = __expf(acc[c][nt][0] - M0);
            float e1 = __expf(acc[c][nt][1] - M0);
            float e2 = __expf(acc[c][nt][2] - M1);
            float e3 = __expf(acc[c][nt][3] - M1);
            acc[c][nt][0] = e0; acc[c][nt][1] = e1;
            acc[c][nt][2] = e2; acc[c][nt][3] = e3;
            s0 += e0 + e1; s1 += e2 + e3;
        }
#pragma unroll
    for (int o = 1; o <= 2; o <<= 1) {
        s0 += __shfl_xor_sync(0xffffffffu, s0, o);
        s1 += __shfl_xor_sync(0xffffffffu, s1, o);
    }
    if (t4 == 0) { wsum[w][g] = s0; wsum[w][g + 8] = s1; }
    __syncthreads();
    float S0 = 0.f, S1 = 0.f;
#pragma unroll
    for (int ww = 0; ww < 8; ww++) { S0 += wsum[ww][g]; S1 += wsum[ww][g + 8]; }
    float inv0 = 1.0f / S0, inv1 = 1.0f / S1;

#pragma unroll
    for (int c = 0; c < 8; c++)
#pragma unroll
        for (int nt = 0; nt < 2; nt++) {
            int col = c * 128 + w * 16 + nt * 8 + 2 * t4;
            __stcs((float2*)&Op[(size_t)g * SDIM + col],
                   make_float2(acc[c][nt][0] * inv0, acc[c][nt][1] * inv0));
            __stcs((float2*)&Op[(size_t)(g + 8) * SDIM + col],
                   make_float2(acc[c][nt][2] * inv1, acc[c][nt][3] * inv1));
        }
}

// ---------------- V transpose + fp16 split: vT[bh][d][s] ------------------
__global__ void vt_kernel()
{
    __shared__ float ts[64][65];
    int bh = blockIdx.y;
    int s0 = blockIdx.x * 64;
    int tid = threadIdx.x;
#pragma unroll
    for (int l = 0; l < 4; l++) {
        int idx = l * 256 + tid;
        int s = idx >> 4, f4 = idx & 15;
        float4 v = *(const float4*)&g_v[((size_t)bh * SDIM + s0 + s) * DDIM + f4 * 4];
        ts[s][f4 * 4 + 0] = v.x; ts[s][f4 * 4 + 1] = v.y;
        ts[s][f4 * 4 + 2] = v.z; ts[s][f4 * 4 + 3] = v.w;
    }
    __syncthreads();
#pragma unroll
    for (int l = 0; l < 4; l++) {
        int idx = l * 256 + tid;
        int d = idx >> 4, sg = (idx & 15) * 4;
        float x0 = ts[sg + 0][d], x1 = ts[sg + 1][d];
        float x2 = ts[sg + 2][d], x3 = ts[sg + 3][d];
        __half h0 = __float2half_rn(x0), h1 = __float2half_rn(x1);
        __half h2 = __float2half_rn(x2), h3 = __float2half_rn(x3);
        size_t o = ((size_t)bh * DDIM + d) * SDIM + s0 + sg;
        *(__half2*)&g_vth[o]     = __half2(h0, h1);
        *(__half2*)&g_vth[o + 2] = __half2(h2, h3);
        *(__half2*)&g_vtl[o] = __half2(__float2half_rn(x0 - __half2float(h0)),
                                       __float2half_rn(x1 - __half2float(h1)));
        *(__half2*)&g_vtl[o + 2] = __half2(__float2half_rn(x2 - __half2float(h2)),
                                           __float2half_rn(x3 - __half2float(h3)));
    }
}

// ---------------- AV: values = attn @ V, fp16 2-term TC -------------------
#define LDSS2 40
__global__ void __launch_bounds__(256, 1) av_tc_kernel(const float* __restrict__ attn)
{
    __shared__ __half Ah[128 * LDSS2];
    __shared__ __half Bh[64 * LDSS2];
    __shared__ __half Bl[64 * LDSS2];

    const int bh = blockIdx.y;
    const int bb = bh >> 4, h = bh & 15;
    const int m0 = blockIdx.x * 128;
    const int tid = threadIdx.x, lane = tid & 31, w = tid >> 5;
    const int wm = w * 16;

    const float* Ap = attn + ((size_t)bh << 20) + (size_t)m0 * SDIM;
    const __half* vhp = g_vth + (size_t)bh * DDIM * SDIM;
    const __half* vlp = g_vtl + (size_t)bh * DDIM * SDIM;

    unsigned aoH, boH[4], boL[4];
    {
        int ar = lane & 15, ak = (lane >> 4) * 8;
        aoH = s2u(Ah) + ((wm + ar) * LDSS2 + ak) * 2;
        int nr = (lane & 7) + ((lane >> 4) & 1) * 8;
        int nk = ((lane >> 3) & 1) * 8;
#pragma unroll
        for (int np = 0; np < 4; np++) {
            boH[np] = s2u(Bh) + ((np * 16 + nr) * LDSS2 + nk) * 2;
            boL[np] = s2u(Bl) + ((np * 16 + nr) * LDSS2 + nk) * 2;
        }
    }

    float acc[8][4];
#pragma unroll
    for (int i = 0; i < 8; i++)
#pragma unroll
        for (int e = 0; e < 4; e++) acc[i][e] = 0.f;

#pragma unroll 1
    for (int k0 = 0; k0 < SDIM; k0 += 32) {
#pragma unroll
        for (int l = 0; l < 4; l++) {
            int idx = l * 256 + tid;
            int m = idx >> 3, kq = (idx & 7) * 4;
            float4 v = __ldcs((const float4*)&Ap[(size_t)m * SDIM + k0 + kq]);
            int o = m * LDSS2 + kq;
            *(__half2*)&Ah[o]     = __floats2half2_rn(v.x, v.y);
            *(__half2*)&Ah[o + 2] = __floats2half2_rn(v.z, v.w);
        }
        {
            int d = tid >> 2, kq = (tid & 3) * 8;
            uint4 hv = *(const uint4*)&vhp[(size_t)d * SDIM + k0 + kq];
            *(uint4*)&Bh[d * LDSS2 + kq] = hv;
            uint4 lv = *(const uint4*)&vlp[(size_t)d * SDIM + k0 + kq];
            *(uint4*)&Bl[d * LDSS2 + kq] = lv;
        }
        __syncthreads();

#pragma unroll
        for (int ks = 0; ks < 2; ks++) {
            unsigned off = ks * 32;
            unsigned ah[4], bhf[8][2], blf[8][2];
            ldsm4(ah, aoH + off);
#pragma unroll
            for (int np = 0; np < 4; np++) {
                unsigned r[4];
                ldsm4(r, boH[np] + off);
                bhf[2 * np][0] = r[0]; bhf[2 * np][1] = r[1];
                bhf[2 * np + 1][0] = r[2]; bhf[2 * np + 1][1] = r[3];
                ldsm4(r, boL[np] + off);
                blf[2 * np][0] = r[0]; blf[2 * np][1] = r[1];
                blf[2 * np + 1][0] = r[2]; blf[2 * np + 1][1] = r[3];
            }
#pragma unroll
            for (int nt = 0; nt < 8; nt++) {
                mma16816h(acc[nt], ah, bhf[nt]);
                mma16816h(acc[nt], ah, blf[nt]);
            }
        }
        __syncthreads();
    }

    const int g = lane >> 2, cq = (lane & 3) * 2;
#pragma unroll
    for (int nt = 0; nt < 8; nt++) {
        int d = nt * 8 + cq;
        int r0 = m0 + wm + g;
        *(float2*)&g_val[((size_t)(bb * SDIM + r0)) * EDIM + h * DDIM + d] =
            make_float2(acc[nt][0], acc[nt][1]);
        *(float2*)&g_val[((size_t)(bb * SDIM + r0 + 8)) * EDIM + h * DDIM + d] =
            make_float2(acc[nt][2], acc[nt][3]);
    }
}

// ---------------- launch ----------------------------------------------
extern "C" void kernel_launch(void* const* d_in, const int* in_sizes, int n_in,
                              void* d_out, int out_size)
{
    const float* x  = (const float*)d_in[0];
    const float* W0 = (const float*)d_in[1];
    const float* b0 = (const float*)d_in[2];
    const float* W1 = (const float*)d_in[3];
    const float* b1 = (const float*)d_in[4];
    const float* W2 = (const float*)d_in[5];
    const float* b2 = (const float*)d_in[6];
    const float* Wv = (const float*)d_in[7];
    const float* bv = (const float*)d_in[8];
    const float* Wo = (const float*)d_in[9];
    const float* bo = (const float*)d_in[10];
    const float* A  = (const float*)d_in[11];

    float* out  = (float*)d_out;
    float* attn = out + (size_t)MTOT * EDIM;

    cudaFuncSetAttribute(gemm_proj_kernel,
                         cudaFuncAttributeMaxDynamicSharedMemorySize, GSMB);
    cudaFuncSetAttribute(gemm_out_kernel,
                         cudaFuncAttributeMaxDynamicSharedMemorySize, GSMB);

    xsum_kernel<<<dim3(4, 4), 256>>>(x);
    gemm_proj_kernel<<<dim3(8, 32, 3), 256, GSMB>>>(x, W0, b0, W1, b1, Wv, bv);

    s2small_kernel<<<dim3(128, 4), 256>>>(W2, b2);
    m_kernel<<<64, 256>>>(A);
    vt_kernel<<<dim3(16, BH), 256>>>();

    lsm_kernel<<<dim3(64, BH), 256>>>(attn);
    av_tc_kernel<<<dim3(8, BH), 256>>>(attn);

    gemm_out_kernel<<<dim3(8, 32), 256, GSMB>>>(Wo, bo, out);
}